// round 5
// baseline (speedup 1.0000x reference)
#include <cuda_runtime.h>
#include <math.h>

#define NSAMP   480000
#define SRATE   48000.0f
#define MAXDEL  50
#define M_PER   25                 // elements per thread in scan kernels
#define PTH     (NSAMP / M_PER)    // 19200 scan threads total
#define BLK     256
#define K1_GRID (PTH / BLK)        // 75 blocks
#define K2_PER  (PTH / BLK)        // 75 partials per scan thread
#define SEG     (BLK * M_PER)      // 6400 elements per block segment

// scratch (static device globals — no allocation)
__device__ float g_part_lo[PTH];
__device__ float g_part_hi[PTH];
__device__ float g_carry_lo[PTH];
__device__ float g_carry_hi[PTH];
__device__ float g_filt[NSAMP];
__device__ unsigned int g_ticket = 0;   // last-block election; reset by the last block itself

struct RParams {
    float a_lo, a_hi, fb, gain;
    int L, nd;
};

__device__ __forceinline__ RParams get_params(const float* __restrict__ p) {
    RParams r;
    float freq = fminf(fmaxf(p[0], 20.0f), SRATE * 0.5f);
    r.fb   = fminf(fmaxf(p[1], 0.0f), 0.99f);
    r.a_lo = fminf(fmaxf(p[2], 1e-7f), 0.99f);
    r.a_hi = fminf(fmaxf(p[3], 1e-7f), 0.99f);
    r.gain = fmaxf(p[4], 1e-7f);
    float dl = floorf(SRATE / freq);
    dl = fminf(fmaxf(dl, 1.0f), (float)(NSAMP / 2));
    r.L = (int)dl;
    int nd = NSAMP / r.L;
    r.nd = nd < MAXDEL ? nd : MAXDEL;
    return r;
}

// ---------------------------------------------------------------------------
// KA = K1 + K2 fused.
// Phase A (all 75 blocks): per-thread local recurrence partials (zero init).
// Phase B (last-arriving block only): affine scan over all 19200 partials ->
// exclusive carries. Affine map per segment: y -> v + D*y (D = d^M_PER).
// ---------------------------------------------------------------------------
__global__ __launch_bounds__(BLK) void ka_partials_scan(
    const float* __restrict__ buf, const float* __restrict__ p)
{
    __shared__ float s[SEG];
    const int base = blockIdx.x * SEG;

    // vectorized smem staging (SEG % 4 == 0, base % 4 == 0)
    {
        const float4* in4 = (const float4*)(buf + base);
        float4* s4 = (float4*)s;
        for (int i = threadIdx.x; i < SEG / 4; i += BLK) s4[i] = in4[i];
    }
    __syncthreads();

    RParams rp = get_params(p);
    const float a_lo = rp.a_lo, d_lo = 1.0f - rp.a_lo;
    const float a_hi = rp.a_hi, d_hi = 1.0f - rp.a_hi;

    float ylo = 0.0f, yhi = 0.0f;
    const int off = threadIdx.x * M_PER;
#pragma unroll
    for (int k = 0; k < M_PER; k++) {
        float x = s[off + k];
        ylo = fmaf(a_lo, x, d_lo * ylo);
        yhi = fmaf(a_hi, x, d_hi * yhi);
    }
    const int g = blockIdx.x * BLK + threadIdx.x;
    g_part_lo[g] = ylo;
    g_part_hi[g] = yhi;

    // ---- last-block election ----
    __threadfence();                       // make partials visible before ticket
    __shared__ int amLast;
    if (threadIdx.x == 0) {
        unsigned int t = atomicAdd(&g_ticket, 1u);
        amLast = (t == (unsigned)(K1_GRID - 1));
    }
    __syncthreads();
    if (!amLast) return;
    __threadfence();                       // acquire: order partial loads after ticket

    // ---- Phase B: global carry scan (this block's 256 threads) ----
    __shared__ float sv_lo[BLK], sv_hi[BLK], sp_lo[BLK], sp_hi[BLK];

    // per-segment decay D = d^M_PER
    float D_lo = 1.0f, D_hi = 1.0f;
#pragma unroll
    for (int k = 0; k < M_PER; k++) { D_lo *= d_lo; D_hi *= d_hi; }

    const int t = threadIdx.x;

    // serially compose this thread's K2_PER consecutive segments
    float Vlo = 0.0f, Vhi = 0.0f;
    float Plo = 1.0f, Phi = 1.0f;
    const int gbase = t * K2_PER;
#pragma unroll 5
    for (int j = 0; j < K2_PER; j++) {
        Vlo = fmaf(D_lo, Vlo, g_part_lo[gbase + j]);
        Vhi = fmaf(D_hi, Vhi, g_part_hi[gbase + j]);
        Plo *= D_lo; Phi *= D_hi;
    }

    sv_lo[t] = Vlo; sv_hi[t] = Vhi;
    sp_lo[t] = Plo; sp_hi[t] = Phi;
    __syncthreads();

    // Hillis-Steele inclusive scan over 256 threads (affine composition)
    for (int sgap = 1; sgap < BLK; sgap <<= 1) {
        float lvlo = 0.0f, lvhi = 0.0f, lplo = 1.0f, lphi = 1.0f;
        if (t >= sgap) {
            lvlo = sv_lo[t - sgap]; lvhi = sv_hi[t - sgap];
            lplo = sp_lo[t - sgap]; lphi = sp_hi[t - sgap];
        }
        float vlo = sv_lo[t], vhi = sv_hi[t];
        float plo = sp_lo[t], phi = sp_hi[t];
        __syncthreads();
        sv_lo[t] = fmaf(plo, lvlo, vlo);
        sv_hi[t] = fmaf(phi, lvhi, vhi);
        sp_lo[t] = plo * lplo;
        sp_hi[t] = phi * lphi;
        __syncthreads();
    }

    // exclusive carry entering this thread's group (zero initial state ->
    // carry = inclusive prefix value of the previous thread)
    float Clo = (t > 0) ? sv_lo[t - 1] : 0.0f;
    float Chi = (t > 0) ? sv_hi[t - 1] : 0.0f;

#pragma unroll 5
    for (int j = 0; j < K2_PER; j++) {
        const int gg = gbase + j;
        g_carry_lo[gg] = Clo;
        g_carry_hi[gg] = Chi;
        Clo = fmaf(D_lo, Clo, g_part_lo[gg]);
        Chi = fmaf(D_hi, Chi, g_part_hi[gg]);
    }

    // reset the ticket for the next graph replay (all blocks already arrived)
    if (t == 0) g_ticket = 0;
}

// ---------------------------------------------------------------------------
// KB: replay recurrence with exact incoming carry, write filtered = y_hi - y_lo
// ---------------------------------------------------------------------------
__global__ __launch_bounds__(BLK) void kb_filter(
    const float* __restrict__ buf, const float* __restrict__ p)
{
    __shared__ float s[SEG];
    const int base = blockIdx.x * SEG;
    {
        const float4* in4 = (const float4*)(buf + base);
        float4* s4 = (float4*)s;
        for (int i = threadIdx.x; i < SEG / 4; i += BLK) s4[i] = in4[i];
    }
    __syncthreads();

    RParams rp = get_params(p);
    const float a_lo = rp.a_lo, d_lo = 1.0f - rp.a_lo;
    const float a_hi = rp.a_hi, d_hi = 1.0f - rp.a_hi;

    const int g = blockIdx.x * BLK + threadIdx.x;
    float ylo = g_carry_lo[g];
    float yhi = g_carry_hi[g];

    const int off = threadIdx.x * M_PER;
#pragma unroll
    for (int k = 0; k < M_PER; k++) {
        float x = s[off + k];
        ylo = fmaf(a_lo, x, d_lo * ylo);
        yhi = fmaf(a_hi, x, d_hi * yhi);
        s[off + k] = yhi - ylo;     // bandpass = hi_lp - lo_lp
    }
    __syncthreads();
    {
        float4* out4 = (float4*)(g_filt + base);
        const float4* s4 = (const float4*)s;
        for (int i = threadIdx.x; i < SEG / 4; i += BLK) out4[i] = s4[i];
    }
}

// ---------------------------------------------------------------------------
// KC: comb-sum + tanh. No data-dependent breaks: precomputed trip count,
// 4 independent accumulators -> high MLP on the L2 gathers.
// ---------------------------------------------------------------------------
__global__ __launch_bounds__(BLK) void kc_output(
    const float* __restrict__ in_sig, const float* __restrict__ p,
    float* __restrict__ out)
{
    const int n = blockIdx.x * BLK + threadIdx.x;
    if (n >= NSAMP) return;

    RParams rp = get_params(p);
    const int L = rp.L;
    const float fb = rp.fb;

    // active taps for this sample: i in [1, imax]
    // (i*L < NSAMP is subsumed by i*L <= n < NSAMP)
    const int imax = min(rp.nd - 1, n / L);

    const float fb2 = fb * fb;
    const float fb3 = fb2 * fb;
    const float fb4 = fb2 * fb2;

    const float* __restrict__ basep = g_filt + n;

    float s0 = 0.0f, s1 = 0.0f, s2 = 0.0f, s3 = 0.0f;
    float w = fb;   // fb^i at loop head
    int i = 1;
    for (; i + 3 <= imax; i += 4) {
        const float* q = basep - i * L;
        float f0 = __ldg(q);
        float f1 = __ldg(q - L);
        float f2 = __ldg(q - 2 * L);
        float f3 = __ldg(q - 3 * L);
        s0 = fmaf(w,        f0, s0);
        s1 = fmaf(w * fb,   f1, s1);
        s2 = fmaf(w * fb2,  f2, s2);
        s3 = fmaf(w * fb3,  f3, s3);
        w *= fb4;
    }
    for (; i <= imax; i++) {
        s0 = fmaf(w, __ldg(basep - i * L), s0);
        w *= fb;
    }

    float sum = in_sig[n] + ((s0 + s1) + (s2 + s3));
    out[n] = tanhf(sum * rp.gain);
}

// ---------------------------------------------------------------------------
extern "C" void kernel_launch(void* const* d_in, const int* in_sizes, int n_in,
                              void* d_out, int out_size)
{
    const float* input_signal = (const float*)d_in[0];
    const float* parameters   = (const float*)d_in[1];
    const float* delay_buffer = (const float*)d_in[2];
    float* out = (float*)d_out;

    ka_partials_scan<<<K1_GRID, BLK>>>(delay_buffer, parameters);
    kb_filter<<<K1_GRID, BLK>>>(delay_buffer, parameters);
    kc_output<<<(NSAMP + BLK - 1) / BLK, BLK>>>(input_signal, parameters, out);
}

// round 6
// speedup vs baseline: 4.8272x; 4.8272x over previous
#include <cuda_runtime.h>
#include <math.h>

#define NSAMP   480000
#define SRATE   48000.0f
#define MAXDEL  50
#define M_PER   25                  // samples per thread in scan kernels
#define BLK     256
#define NBLK    75                  // NSAMP / (BLK*M_PER)
#define SEG     (BLK * M_PER)       // 6400 samples per block

// scratch (static device globals — no allocation)
__device__ float g_bpart_lo[NBLK];
__device__ float g_bpart_hi[NBLK];
__device__ float g_bcar_lo[NBLK];
__device__ float g_bcar_hi[NBLK];
__device__ float g_filt[NSAMP];
__device__ unsigned int g_ticket = 0;   // last-block election; reset by the last block

struct RParams {
    float a_lo, a_hi, fb, gain;
    int L, nd;
};

__device__ __forceinline__ RParams get_params(const float* __restrict__ p) {
    RParams r;
    float freq = fminf(fmaxf(p[0], 20.0f), SRATE * 0.5f);
    r.fb   = fminf(fmaxf(p[1], 0.0f), 0.99f);
    r.a_lo = fminf(fmaxf(p[2], 1e-7f), 0.99f);
    r.a_hi = fminf(fmaxf(p[3], 1e-7f), 0.99f);
    r.gain = fmaxf(p[4], 1e-7f);
    float dl = floorf(SRATE / freq);
    dl = fminf(fmaxf(dl, 1.0f), (float)(NSAMP / 2));
    r.L = (int)dl;
    int nd = NSAMP / r.L;
    r.nd = nd < MAXDEL ? nd : MAXDEL;
    return r;
}

// ---------------------------------------------------------------------------
// KA: per-block affine scan -> one block partial per block; last-arriving
// block scans the 75 block partials into exclusive block carries.
// Affine per-thread map: y -> v_t + D*y with the SAME D = d^25 for all
// threads, so the Hillis-Steele multipliers form a scalar square ladder.
// ---------------------------------------------------------------------------
__global__ __launch_bounds__(BLK) void ka_block_partials(
    const float* __restrict__ buf, const float* __restrict__ p)
{
    __shared__ float s[SEG];
    __shared__ float sv_lo[BLK], sv_hi[BLK];

    const int t = threadIdx.x;
    const int base = blockIdx.x * SEG;
    {
        const float4* in4 = (const float4*)(buf + base);
        float4* s4 = (float4*)s;
        for (int i = t; i < SEG / 4; i += BLK) s4[i] = in4[i];
    }
    __syncthreads();

    RParams rp = get_params(p);
    const float a_lo = rp.a_lo, d_lo = 1.0f - rp.a_lo;
    const float a_hi = rp.a_hi, d_hi = 1.0f - rp.a_hi;

    float ylo = 0.0f, yhi = 0.0f;
    const int off = t * M_PER;
#pragma unroll
    for (int k = 0; k < M_PER; k++) {
        float x = s[off + k];
        ylo = fmaf(a_lo, x, d_lo * ylo);
        yhi = fmaf(a_hi, x, d_hi * yhi);
    }
    sv_lo[t] = ylo;
    sv_hi[t] = yhi;

    // D = d^M_PER
    float Plo = 1.0f, Phi = 1.0f;
#pragma unroll
    for (int k = 0; k < M_PER; k++) { Plo *= d_lo; Phi *= d_hi; }
    __syncthreads();

    // in-block inclusive affine scan (8 rounds, scalar multiplier ladder)
#pragma unroll
    for (int r = 0; r < 8; r++) {
        const int gap = 1 << r;
        float mylo = sv_lo[t], myhi = sv_hi[t];
        float olo = 0.0f, ohi = 0.0f;
        if (t >= gap) { olo = sv_lo[t - gap]; ohi = sv_hi[t - gap]; }
        __syncthreads();
        sv_lo[t] = fmaf(Plo, olo, mylo);
        sv_hi[t] = fmaf(Phi, ohi, myhi);
        __syncthreads();
        Plo *= Plo; Phi *= Phi;     // after 8 rounds: Plo = D^256 (block decay)
    }

    if (t == BLK - 1) {
        g_bpart_lo[blockIdx.x] = sv_lo[t];
        g_bpart_hi[blockIdx.x] = sv_hi[t];
    }

    // ---- last-block election ----
    __threadfence();
    __shared__ int amLast;
    if (t == 0) {
        unsigned int tk = atomicAdd(&g_ticket, 1u);
        amLast = (tk == (unsigned)(NBLK - 1));
    }
    __syncthreads();
    if (!amLast) return;
    __threadfence();

    // ---- phase B: scan 75 block partials (multiplier = block decay) ----
    float vlo = (t < NBLK) ? g_bpart_lo[t] : 0.0f;
    float vhi = (t < NBLK) ? g_bpart_hi[t] : 0.0f;
    sv_lo[t] = vlo;
    sv_hi[t] = vhi;
    __syncthreads();

#pragma unroll
    for (int r = 0; r < 8; r++) {
        const int gap = 1 << r;
        float mylo = sv_lo[t], myhi = sv_hi[t];
        float olo = 0.0f, ohi = 0.0f;
        if (t >= gap) { olo = sv_lo[t - gap]; ohi = sv_hi[t - gap]; }
        __syncthreads();
        sv_lo[t] = fmaf(Plo, olo, mylo);
        sv_hi[t] = fmaf(Phi, ohi, myhi);
        __syncthreads();
        Plo *= Plo; Phi *= Phi;
    }

    if (t < NBLK) {
        g_bcar_lo[t] = (t == 0) ? 0.0f : sv_lo[t - 1];
        g_bcar_hi[t] = (t == 0) ? 0.0f : sv_hi[t - 1];
    }
    if (t == 0) g_ticket = 0;   // reset for next graph replay
}

// ---------------------------------------------------------------------------
// KB: recompute thread partials, in-block exclusive scan + block carry,
// replay recurrence, write filtered = y_hi - y_lo (all coalesced).
// ---------------------------------------------------------------------------
__global__ __launch_bounds__(BLK) void kb_filter(
    const float* __restrict__ buf, const float* __restrict__ p)
{
    __shared__ float s[SEG];
    __shared__ float sv_lo[BLK], sv_hi[BLK];

    const int t = threadIdx.x;
    const int base = blockIdx.x * SEG;
    {
        const float4* in4 = (const float4*)(buf + base);
        float4* s4 = (float4*)s;
        for (int i = t; i < SEG / 4; i += BLK) s4[i] = in4[i];
    }
    __syncthreads();

    RParams rp = get_params(p);
    const float a_lo = rp.a_lo, d_lo = 1.0f - rp.a_lo;
    const float a_hi = rp.a_hi, d_hi = 1.0f - rp.a_hi;

    float ylo = 0.0f, yhi = 0.0f;
    const int off = t * M_PER;
#pragma unroll
    for (int k = 0; k < M_PER; k++) {
        float x = s[off + k];
        ylo = fmaf(a_lo, x, d_lo * ylo);
        yhi = fmaf(a_hi, x, d_hi * yhi);
    }
    sv_lo[t] = ylo;
    sv_hi[t] = yhi;

    float Plo = 1.0f, Phi = 1.0f;
#pragma unroll
    for (int k = 0; k < M_PER; k++) { Plo *= d_lo; Phi *= d_hi; }
    __syncthreads();

    // inclusive scan; save multiplier ladder for D^t reconstruction
    float lad_lo[8], lad_hi[8];
#pragma unroll
    for (int r = 0; r < 8; r++) {
        const int gap = 1 << r;
        lad_lo[r] = Plo; lad_hi[r] = Phi;
        float mylo = sv_lo[t], myhi = sv_hi[t];
        float olo = 0.0f, ohi = 0.0f;
        if (t >= gap) { olo = sv_lo[t - gap]; ohi = sv_hi[t - gap]; }
        __syncthreads();
        sv_lo[t] = fmaf(Plo, olo, mylo);
        sv_hi[t] = fmaf(Phi, ohi, myhi);
        __syncthreads();
        Plo *= Plo; Phi *= Phi;
    }

    // exclusive prefix value for this thread
    float vex_lo = (t == 0) ? 0.0f : sv_lo[t - 1];
    float vex_hi = (t == 0) ? 0.0f : sv_hi[t - 1];

    // D^t from the ladder (binary exponentiation over bits of t)
    float pex_lo = 1.0f, pex_hi = 1.0f;
#pragma unroll
    for (int r = 0; r < 8; r++) {
        if ((t >> r) & 1) { pex_lo *= lad_lo[r]; pex_hi *= lad_hi[r]; }
    }

    // state entering this thread's segment = vex + D^t * (block carry)
    const float Cb_lo = g_bcar_lo[blockIdx.x];
    const float Cb_hi = g_bcar_hi[blockIdx.x];
    ylo = fmaf(pex_lo, Cb_lo, vex_lo);
    yhi = fmaf(pex_hi, Cb_hi, vex_hi);

    __syncthreads();   // done reading sv arrays; s[] rewritten below
#pragma unroll
    for (int k = 0; k < M_PER; k++) {
        float x = s[off + k];
        ylo = fmaf(a_lo, x, d_lo * ylo);
        yhi = fmaf(a_hi, x, d_hi * yhi);
        s[off + k] = yhi - ylo;     // bandpass = hi_lp - lo_lp
    }
    __syncthreads();
    {
        float4* out4 = (float4*)(g_filt + base);
        const float4* s4 = (const float4*)s;
        for (int i = t; i < SEG / 4; i += BLK) out4[i] = s4[i];
    }
}

// ---------------------------------------------------------------------------
// KC: comb-sum + tanh. Precomputed trip count, 4 independent accumulators
// for high MLP on the L2 gathers.
// ---------------------------------------------------------------------------
__global__ __launch_bounds__(BLK) void kc_output(
    const float* __restrict__ in_sig, const float* __restrict__ p,
    float* __restrict__ out)
{
    const int n = blockIdx.x * BLK + threadIdx.x;
    if (n >= NSAMP) return;

    RParams rp = get_params(p);
    const int L = rp.L;
    const float fb = rp.fb;

    // active taps: i in [1, imax]  (i*L < NSAMP subsumed by i*L <= n)
    const int imax = min(rp.nd - 1, n / L);

    const float fb2 = fb * fb;
    const float fb3 = fb2 * fb;
    const float fb4 = fb2 * fb2;

    const float* __restrict__ basep = g_filt + n;

    float s0 = 0.0f, s1 = 0.0f, s2 = 0.0f, s3 = 0.0f;
    float w = fb;
    int i = 1;
    for (; i + 3 <= imax; i += 4) {
        const float* q = basep - i * L;
        float f0 = __ldg(q);
        float f1 = __ldg(q - L);
        float f2 = __ldg(q - 2 * L);
        float f3 = __ldg(q - 3 * L);
        s0 = fmaf(w,       f0, s0);
        s1 = fmaf(w * fb,  f1, s1);
        s2 = fmaf(w * fb2, f2, s2);
        s3 = fmaf(w * fb3, f3, s3);
        w *= fb4;
    }
    for (; i <= imax; i++) {
        s0 = fmaf(w, __ldg(basep - i * L), s0);
        w *= fb;
    }

    float sum = in_sig[n] + ((s0 + s1) + (s2 + s3));
    out[n] = tanhf(sum * rp.gain);
}

// ---------------------------------------------------------------------------
extern "C" void kernel_launch(void* const* d_in, const int* in_sizes, int n_in,
                              void* d_out, int out_size)
{
    const float* input_signal = (const float*)d_in[0];
    const float* parameters   = (const float*)d_in[1];
    const float* delay_buffer = (const float*)d_in[2];
    float* out = (float*)d_out;

    ka_block_partials<<<NBLK, BLK>>>(delay_buffer, parameters);
    kb_filter<<<NBLK, BLK>>>(delay_buffer, parameters);
    kc_output<<<(NSAMP + BLK - 1) / BLK, BLK>>>(input_signal, parameters, out);
}

// round 8
// speedup vs baseline: 5.5961x; 1.1593x over previous
#include <cuda_runtime.h>
#include <math.h>

#define NSAMP   480000
#define SRATE   48000.0f
#define MAXDEL  50
#define BLK     256
#define NBLK    125                 // <= 148 SMs -> all CTAs co-resident (grid-sync safe)
#define M_PER   15                  // NSAMP / (NBLK*BLK)
#define SEG     (BLK * M_PER)       // 3840 samples per block

// comb fast-path constants (hold for this dataset: p0 in [0,1) -> freq clips to 20)
#define CHN     2400                // L
#define CLEN    200                 // NSAMP / L
#define NDEL    50                  // min(CLEN, MAXDEL)
#define PQ      13                  // subchains per chain
#define SUBLEN  16                  // ceil(CLEN / PQ)

// scratch (static device globals — no allocation)
__device__ float g_bpart_lo[NBLK];
__device__ float g_bpart_hi[NBLK];
__device__ float g_filt[NSAMP];
__device__ unsigned int g_bar0 = 0;
__device__ unsigned int g_bar1 = 0;
__device__ unsigned int g_bar2 = 0;

struct RParams {
    float a_lo, a_hi, fb, gain;
    int L, nd;
};

__device__ __forceinline__ RParams get_params(const float* __restrict__ p) {
    RParams r;
    float freq = fminf(fmaxf(p[0], 20.0f), SRATE * 0.5f);
    r.fb   = fminf(fmaxf(p[1], 0.0f), 0.99f);
    r.a_lo = fminf(fmaxf(p[2], 1e-7f), 0.99f);
    r.a_hi = fminf(fmaxf(p[3], 1e-7f), 0.99f);
    r.gain = fmaxf(p[4], 1e-7f);
    float dl = floorf(SRATE / freq);
    dl = fminf(fmaxf(dl, 1.0f), (float)(NSAMP / 2));
    r.L = (int)dl;
    int nd = NSAMP / r.L;
    r.nd = nd < MAXDEL ? nd : MAXDEL;
    return r;
}

// grid-wide barrier: all 125 CTAs are resident, so spinning is deadlock-free.
__device__ __forceinline__ void grid_barrier(unsigned int* ctr) {
    __threadfence();                 // publish this block's global writes
    __syncthreads();
    if (threadIdx.x == 0) {
        atomicAdd(ctr, 1u);
        while (*(volatile unsigned int*)ctr < (unsigned)NBLK) { }
    }
    __syncthreads();
    __threadfence();                 // acquire other blocks' writes
}

__global__ __launch_bounds__(BLK) void resonator_fused(
    const float* __restrict__ in_sig, const float* __restrict__ p,
    const float* __restrict__ buf, float* __restrict__ out)
{
    __shared__ float s[SEG];
    __shared__ float sv_lo[BLK], sv_hi[BLK];
    __shared__ float s_carry[2];

    const int t = threadIdx.x;
    const int b = blockIdx.x;
    const int base = b * SEG;

    // ---- stage raw segment (float4, coalesced) ----
    {
        const float4* in4 = (const float4*)(buf + base);
        float4* s4 = (float4*)s;
        for (int i = t; i < SEG / 4; i += BLK) s4[i] = in4[i];
    }
    __syncthreads();

    const RParams rp = get_params(p);
    const float a_lo = rp.a_lo, d_lo = 1.0f - rp.a_lo;
    const float a_hi = rp.a_hi, d_hi = 1.0f - rp.a_hi;

    // ---- phase 1: per-thread partials (zero init), in-block affine scan ----
    {
        float ylo = 0.0f, yhi = 0.0f;
        const int off = t * M_PER;
#pragma unroll
        for (int k = 0; k < M_PER; k++) {
            float x = s[off + k];
            ylo = fmaf(a_lo, x, d_lo * ylo);
            yhi = fmaf(a_hi, x, d_hi * yhi);
        }
        sv_lo[t] = ylo;
        sv_hi[t] = yhi;
    }

    // D = d^M_PER
    float Plo = 1.0f, Phi = 1.0f;
#pragma unroll
    for (int k = 0; k < M_PER; k++) { Plo *= d_lo; Phi *= d_hi; }
    __syncthreads();

    float lad_lo[8], lad_hi[8];
#pragma unroll
    for (int r = 0; r < 8; r++) {
        lad_lo[r] = Plo; lad_hi[r] = Phi;           // D^(2^r)
        const int gap = 1 << r;
        float mylo = sv_lo[t], myhi = sv_hi[t];
        float olo = 0.0f, ohi = 0.0f;
        if (t >= gap) { olo = sv_lo[t - gap]; ohi = sv_hi[t - gap]; }
        __syncthreads();
        sv_lo[t] = fmaf(Plo, olo, mylo);
        sv_hi[t] = fmaf(Phi, ohi, myhi);
        __syncthreads();
        Plo *= Plo; Phi *= Phi;                     // ends at D^256 (block decay)
    }

    // exclusive prefix + D^t (into registers BEFORE sv gets reused)
    const float vex_lo = (t == 0) ? 0.0f : sv_lo[t - 1];
    const float vex_hi = (t == 0) ? 0.0f : sv_hi[t - 1];
    float pex_lo = 1.0f, pex_hi = 1.0f;
#pragma unroll
    for (int r = 0; r < 8; r++)
        if ((t >> r) & 1) { pex_lo *= lad_lo[r]; pex_hi *= lad_hi[r]; }

    if (t == BLK - 1) {
        g_bpart_lo[b] = sv_lo[t];
        g_bpart_hi[b] = sv_hi[t];
    }

    grid_barrier(&g_bar0);

    // ---- phase 2: block carry (stage partials into smem, serial scan) ----
    if (t < NBLK) { sv_lo[t] = g_bpart_lo[t]; sv_hi[t] = g_bpart_hi[t]; }
    __syncthreads();
    if (t == 0) {
        float Clo = 0.0f, Chi = 0.0f;
        for (int k = 0; k < b; k++) {
            Clo = fmaf(Plo, Clo, sv_lo[k]);         // Plo = D^256 = block decay
            Chi = fmaf(Phi, Chi, sv_hi[k]);
        }
        s_carry[0] = Clo; s_carry[1] = Chi;
    }
    __syncthreads();

    // ---- replay with exact carry, write filtered = y_hi - y_lo ----
    {
        float ylo = fmaf(pex_lo, s_carry[0], vex_lo);
        float yhi = fmaf(pex_hi, s_carry[1], vex_hi);
        const int off = t * M_PER;
#pragma unroll
        for (int k = 0; k < M_PER; k++) {
            float x = s[off + k];
            ylo = fmaf(a_lo, x, d_lo * ylo);
            yhi = fmaf(a_hi, x, d_hi * yhi);
            s[off + k] = yhi - ylo;
        }
    }
    __syncthreads();
    {
        float4* f4 = (float4*)(g_filt + base);
        const float4* s4 = (const float4*)s;
        for (int i = t; i < SEG / 4; i += BLK) f4[i] = s4[i];
    }

    grid_barrier(&g_bar1);

    // ---- phase 3: comb + tanh ----
    const float fb = rp.fb, gain = rp.gain;
    const int gtid = b * BLK + t;

    if (rp.L == CHN && rp.nd == NDEL) {
        // fast path: stride-L chain recurrence
        // T[j] = fb*(f[j-1] + T[j-1]) - fb^50 * f[j-50]   (tail term when j>=50)
        if (gtid < CHN * PQ) {
            const int q = gtid / CHN;               // subchain index in chain
            const int c = gtid % CHN;               // chain id (coalesced across warp)
            const int j0 = q * SUBLEN;
            const int j1 = min(j0 + SUBLEN, CLEN);

            // fb^50 by squaring: fb^25 = fb^16 * fb^8 * fb
            const float fp2 = fb * fb;
            const float fp4 = fp2 * fp2;
            const float fp8 = fp4 * fp4;
            const float fp16 = fp8 * fp8;
            const float fb25 = fp16 * fp8 * fb;
            const float fb50 = fb25 * fb25;

            const float* __restrict__ fc = g_filt + c;

            // startup: T[j0] = sum_{i=1..min(49,j0)} fb^i f[j0-i]  (direct gather, MLP=4)
            float T;
            {
                const int im = min(NDEL - 1, j0);
                float s0 = 0.0f, s1 = 0.0f, s2 = 0.0f, s3 = 0.0f;
                const float fb2 = fp2, fb3 = fp2 * fb, fb4 = fp4;
                float w = fb;
                int i = 1;
                for (; i + 3 <= im; i += 4) {
                    const float* qp = fc + (j0 - i) * CHN;
                    float v0 = __ldg(qp);
                    float v1 = __ldg(qp - CHN);
                    float v2 = __ldg(qp - 2 * CHN);
                    float v3 = __ldg(qp - 3 * CHN);
                    s0 = fmaf(w,       v0, s0);
                    s1 = fmaf(w * fb,  v1, s1);
                    s2 = fmaf(w * fb2, v2, s2);
                    s3 = fmaf(w * fb3, v3, s3);
                    w *= fb4;
                }
                for (; i <= im; i++) {
                    s0 = fmaf(w, __ldg(fc + (j0 - i) * CHN), s0);
                    w *= fb;
                }
                T = (s0 + s1) + (s2 + s3);
            }
            {
                const int n = c + j0 * CHN;
                out[n] = tanhf((__ldg(in_sig + n) + T) * gain);
            }

            // recurrence over the subchain
            float fj = __ldg(fc + j0 * CHN);        // f[j-1] for j = j0+1
            for (int j = j0 + 1; j < j1; j++) {
                float tail = (j >= NDEL) ? __ldg(fc + (j - NDEL) * CHN) : 0.0f;
                T = fmaf(fb, fj + T, -fb50 * tail);
                const int n = c + j * CHN;
                float fnext = __ldg(fc + j * CHN);  // f[j] for next iter
                out[n] = tanhf((__ldg(in_sig + n) + T) * gain);
                fj = fnext;
            }
        }
    } else {
        // generic fallback: direct gather, grid-stride
        const int L = rp.L;
        const float fb2 = fb * fb, fb3 = fb2 * fb, fb4 = fb2 * fb2;
        for (int n = gtid; n < NSAMP; n += NBLK * BLK) {
            const int imax = min(rp.nd - 1, n / L);
            const float* __restrict__ basep = g_filt + n;
            float s0 = 0.0f, s1 = 0.0f, s2 = 0.0f, s3 = 0.0f;
            float w = fb;
            int i = 1;
            for (; i + 3 <= imax; i += 4) {
                const float* qp = basep - i * L;
                s0 = fmaf(w,       __ldg(qp),         s0);
                s1 = fmaf(w * fb,  __ldg(qp - L),     s1);
                s2 = fmaf(w * fb2, __ldg(qp - 2 * L), s2);
                s3 = fmaf(w * fb3, __ldg(qp - 3 * L), s3);
                w *= fb4;
            }
            for (; i <= imax; i++) {
                s0 = fmaf(w, __ldg(basep - i * L), s0);
                w *= fb;
            }
            float sum = __ldg(in_sig + n) + ((s0 + s1) + (s2 + s3));
            out[n] = tanhf(sum * gain);
        }
    }

    // ---- reset barriers for the next graph replay (last block to finish) ----
    __syncthreads();
    if (t == 0) {
        unsigned int tk = atomicAdd(&g_bar2, 1u);
        if (tk == (unsigned)(NBLK - 1)) {
            g_bar0 = 0; g_bar1 = 0; g_bar2 = 0;
        }
    }
}

// ---------------------------------------------------------------------------
extern "C" void kernel_launch(void* const* d_in, const int* in_sizes, int n_in,
                              void* d_out, int out_size)
{
    const float* input_signal = (const float*)d_in[0];
    const float* parameters   = (const float*)d_in[1];
    const float* delay_buffer = (const float*)d_in[2];
    float* out = (float*)d_out;

    resonator_fused<<<NBLK, BLK>>>(input_signal, parameters, delay_buffer, out);
}